// round 13
// baseline (speedup 1.0000x reference)
#include <cuda_runtime.h>
#include <math.h>

// Batched FFT: B=8192 rows, N=4096, complex fp32 (separate re/im), out = [Yre; Yim].
//
// Radix-16^3 four-step, packed f32x2 arithmetic, binary-decomposition twiddles
// (round-12 math, 82.4us). Round 13: TWO ROWS SEQUENTIALLY per one-shot CTA.
//   Row A: identical to r12 (LDG burst -> 3 passes).
//   After A's exch-2 reads (smem free): cp.async.cg row B input into the SAME
//   smem buffer, overlapping A's pass 3 + stores. Row B then starts from smem
//   (LDS) with zero exposed DRAM latency. Wave count halves (13.8 -> 6.9).
// Registers stay ~52-56 (single v[16] set), 4 CTAs/SM, one-shot scheduling.
//
//   n = n1*256 + n2, k = k2*16 + k1, n2 = p1*16 + p2, k2 = q2*16 + q1.
// Pass 1 (t=n2):   A[k1] = DFT16_{n1}(x[n1*256+t]) * W4096^{t*k1}
// Exch 1 (pad 257)
// Pass 2 (k1,p2):  C[q1] = DFT16_{p1}(...) * W256^{p2*q1}
// Exch 2 ([q1*256+t])
// Pass 3 (k1,q1):  Y[q2*256 + t] = DFT16_{p2}(...)

#define NFFT 4096
#define TPB  256

typedef unsigned long long c64;   // packed complex: lo 32 = re, hi 32 = im

__device__ __forceinline__ c64 cpack(float re, float im) {
    c64 r;
    asm("mov.b64 %0, {%1, %2};" : "=l"(r) : "f"(re), "f"(im));
    return r;
}
__device__ __forceinline__ void cunpack(c64 v, float& re, float& im) {
    asm("mov.b64 {%0, %1}, %2;" : "=f"(re), "=f"(im) : "l"(v));
}
__device__ __forceinline__ c64 padd(c64 a, c64 b) {
    c64 r;
    asm("add.rn.f32x2 %0, %1, %2;" : "=l"(r) : "l"(a), "l"(b));
    return r;
}
__device__ __forceinline__ c64 pmul(c64 a, c64 b) {
    c64 r;
    asm("mul.rn.f32x2 %0, %1, %2;" : "=l"(r) : "l"(a), "l"(b));
    return r;
}
__device__ __forceinline__ c64 pfma(c64 a, c64 b, c64 c) {
    c64 r;
    asm("fma.rn.f32x2 %0, %1, %2, %3;" : "=l"(r) : "l"(a), "l"(b), "l"(c));
    return r;
}
__device__ __forceinline__ c64 pswap(c64 a) {   // (re,im) -> (im,re)
    c64 r;
    asm("{\n\t.reg .b32 lo, hi;\n\tmov.b64 {lo, hi}, %1;\n\tmov.b64 %0, {hi, lo};\n\t}"
        : "=l"(r) : "l"(a));
    return r;
}

#define K_NEG1 cpack(-1.0f, -1.0f)
#define K_PM   cpack( 1.0f, -1.0f)
#define K_MP   cpack(-1.0f,  1.0f)

__device__ __forceinline__ c64 psub(c64 a, c64 b) { return pfma(b, K_NEG1, a); }
// complex mul by twiddle held split: xx=(c,c), nyy=(-s,s)
__device__ __forceinline__ c64 cmul_t(c64 a, c64 xx, c64 nyy) {
    return pfma(a, xx, pmul(pswap(a), nyy));
}
// multiply by -i
__device__ __forceinline__ c64 cnegi(c64 a) { return pmul(pswap(a), K_PM); }

__device__ __forceinline__ void cp_async16(unsigned dst, const void* src) {
    asm volatile("cp.async.cg.shared.global [%0], [%1], 16;"
                 :: "r"(dst), "l"(src) : "memory");
}

// forward DFT4 (W4 = -i), packed
__device__ __forceinline__ void dft4(c64 a, c64 b, c64 c, c64 d,
                                     c64& o0, c64& o1, c64& o2, c64& o3) {
    c64 s0 = padd(a, c);
    c64 s1 = psub(a, c);
    c64 s2 = padd(b, d);
    c64 s3 = psub(b, d);
    o0 = padd(s0, s2);
    o2 = psub(s0, s2);
    c64 s3r = pswap(s3);
    o1 = pfma(s3r, K_PM, s1);   // s1 - i*s3
    o3 = pfma(s3r, K_MP, s1);   // s1 + i*s3
}

// 16-point forward DFT, natural in -> natural out (radix-4 x radix-4), packed.
__device__ __forceinline__ void fft16(c64 v[16]) {
    const float C1 = 0.92387953251128675613f;  // cos(pi/8)
    const float S1 = 0.38268343236508977173f;  // sin(pi/8)
    const float R  = 0.70710678118654752440f;  // sqrt(2)/2

    c64 a[4][4];
#pragma unroll
    for (int l = 0; l < 4; l++)
        dft4(v[l], v[l + 4], v[l + 8], v[l + 12],
             a[l][0], a[l][1], a[l][2], a[l][3]);

    a[1][1] = cmul_t(a[1][1], cpack( C1,  C1), cpack( S1, -S1));
    a[1][2] = cmul_t(a[1][2], cpack(  R,   R), cpack(  R,  -R));
    a[1][3] = cmul_t(a[1][3], cpack( S1,  S1), cpack( C1, -C1));
    a[2][1] = cmul_t(a[2][1], cpack(  R,   R), cpack(  R,  -R));
    a[2][2] = cnegi(a[2][2]);
    a[2][3] = cmul_t(a[2][3], cpack( -R,  -R), cpack(  R,  -R));
    a[3][1] = cmul_t(a[3][1], cpack( S1,  S1), cpack( C1, -C1));
    a[3][2] = cmul_t(a[3][2], cpack( -R,  -R), cpack(  R,  -R));
    a[3][3] = cmul_t(a[3][3], cpack(-C1, -C1), cpack(-S1,  S1));

#pragma unroll
    for (int p = 0; p < 4; p++)
        dft4(a[0][p], a[1][p], a[2][p], a[3][p],
             v[p], v[4 + p], v[8 + p], v[12 + p]);
}

// v[k] *= w^k, k=1..15, via binary decomposition (no serial chain).
__device__ __forceinline__ void twiddle16_bits(c64 v[16], float ang) {
    float s, c;
    __sincosf(ang, &s, &c);                       // MUFU; |ang| < 0.4
    float c2 = fmaf(c,  c,  -s  * s ),  s2 = 2.0f * c  * s;
    float c4 = fmaf(c2, c2, -s2 * s2),  s4 = 2.0f * c2 * s2;
    float c8 = fmaf(c4, c4, -s4 * s4),  s8 = 2.0f * c4 * s4;

    {
        const c64 xx = cpack(c, c), nn = cpack(-s, s);
#pragma unroll
        for (int k = 1; k < 16; k += 2)
            v[k] = cmul_t(v[k], xx, nn);
    }
    {
        const c64 xx = cpack(c2, c2), nn = cpack(-s2, s2);
#pragma unroll
        for (int k = 2; k < 16; k += 4) {
            v[k]     = cmul_t(v[k],     xx, nn);
            v[k + 1] = cmul_t(v[k + 1], xx, nn);
        }
    }
    {
        const c64 xx = cpack(c4, c4), nn = cpack(-s4, s4);
#pragma unroll
        for (int k = 4; k < 8; k++) {
            v[k]     = cmul_t(v[k],     xx, nn);
            v[k + 8] = cmul_t(v[k + 8], xx, nn);
        }
    }
    {
        const c64 xx = cpack(c8, c8), nn = cpack(-s8, s8);
#pragma unroll
        for (int k = 8; k < 16; k++)
            v[k] = cmul_t(v[k], xx, nn);
    }
}

__global__ void __launch_bounds__(TPB, 4)
fft4096_x2seq(const float* __restrict__ xre,
              const float* __restrict__ xim,
              float* __restrict__ out,
              int batch) {
    __shared__ c64 sh[16 * 257];   // exchange buffer; aliased as row-B staging
    float* S = (float*)sh;         // staging: re [0,4096), im [4096,8192) floats

    const int b  = blockIdx.x;
    const int t  = threadIdx.x;
    const int k1 = t & 15;
    const int hi = t >> 4;         // p2 in pass 2, q1 in pass 3
    const int r0 = 2 * b;
    const int r1 = 2 * b + 1;

    const float ang1 = (float)t  * (-6.2831853071795864769f / 4096.0f);
    const float ang2 = (float)hi * (-6.2831853071795864769f /  256.0f);

    // =================== ROW A (global loads) ===================
    const float* xr = xre + (size_t)r0 * NFFT;
    const float* xi = xim + (size_t)r0 * NFFT;

    c64 v[16];
#pragma unroll
    for (int n1 = 0; n1 < 16; n1++)
        v[n1] = cpack(__ldcs(&xr[n1 * 256 + t]), __ldcs(&xi[n1 * 256 + t]));

    fft16(v);
    twiddle16_bits(v, ang1);

#pragma unroll
    for (int k = 0; k < 16; k++)
        sh[k * 257 + t] = v[k];
    __syncthreads();
#pragma unroll
    for (int p1 = 0; p1 < 16; p1++)
        v[p1] = sh[k1 * 257 + p1 * 16 + hi];

    fft16(v);
    twiddle16_bits(v, ang2);
    __syncthreads();

#pragma unroll
    for (int q1 = 0; q1 < 16; q1++)
        sh[q1 * 256 + t] = v[q1];
    __syncthreads();
#pragma unroll
    for (int p2 = 0; p2 < 16; p2++)
        v[p2] = sh[hi * 256 + p2 * 16 + k1];

    __syncthreads();   // all exch-2 reads done -> smem free for row-B staging

    // prefetch row B into smem, overlapping pass-3 A + stores A
    {
        unsigned sb = (unsigned)__cvta_generic_to_shared(S);
        const char* gre = (const char*)(xre + (size_t)r1 * NFFT);
        const char* gim = (const char*)(xim + (size_t)r1 * NFFT);
#pragma unroll
        for (int j = 0; j < 4; j++) {
            cp_async16(sb + (unsigned)((j * 256 + t) * 16),         gre + (j * 256 + t) * 16);
            cp_async16(sb + 16384u + (unsigned)((j * 256 + t) * 16), gim + (j * 256 + t) * 16);
        }
        asm volatile("cp.async.commit_group;" ::: "memory");
    }

    fft16(v);

    {
        float* outre = out + (size_t)r0 * NFFT;
        float* outim = out + (size_t)batch * NFFT + (size_t)r0 * NFFT;
#pragma unroll
        for (int q2 = 0; q2 < 16; q2++) {
            float re, im;
            cunpack(v[q2], re, im);
            __stcs(&outre[q2 * 256 + t], re);
            __stcs(&outim[q2 * 256 + t], im);
        }
    }

    // =================== ROW B (smem-staged input) ===================
    asm volatile("cp.async.wait_group 0;" ::: "memory");
    __syncthreads();

#pragma unroll
    for (int n1 = 0; n1 < 16; n1++)
        v[n1] = cpack(S[n1 * 256 + t], S[4096 + n1 * 256 + t]);

    fft16(v);
    twiddle16_bits(v, ang1);

    __syncthreads();   // staged reads done -> exch-1 may overwrite

#pragma unroll
    for (int k = 0; k < 16; k++)
        sh[k * 257 + t] = v[k];
    __syncthreads();
#pragma unroll
    for (int p1 = 0; p1 < 16; p1++)
        v[p1] = sh[k1 * 257 + p1 * 16 + hi];

    fft16(v);
    twiddle16_bits(v, ang2);
    __syncthreads();

#pragma unroll
    for (int q1 = 0; q1 < 16; q1++)
        sh[q1 * 256 + t] = v[q1];
    __syncthreads();
#pragma unroll
    for (int p2 = 0; p2 < 16; p2++)
        v[p2] = sh[hi * 256 + p2 * 16 + k1];

    fft16(v);

    {
        float* outre = out + (size_t)r1 * NFFT;
        float* outim = out + (size_t)batch * NFFT + (size_t)r1 * NFFT;
#pragma unroll
        for (int q2 = 0; q2 < 16; q2++) {
            float re, im;
            cunpack(v[q2], re, im);
            __stcs(&outre[q2 * 256 + t], re);
            __stcs(&outim[q2 * 256 + t], im);
        }
    }
}

extern "C" void kernel_launch(void* const* d_in, const int* in_sizes, int n_in,
                              void* d_out, int out_size) {
    const float* xre = (const float*)d_in[0];
    const float* xim = (const float*)d_in[1];
    float* out = (float*)d_out;
    const int batch = in_sizes[0] / NFFT;

    fft4096_x2seq<<<batch / 2, TPB>>>(xre, xim, out, batch);
}

// round 14
// speedup vs baseline: 1.0343x; 1.0343x over previous
#include <cuda_runtime.h>
#include <math.h>

// Batched FFT: B=8192 rows, N=4096, complex fp32 (separate re/im), out = [Yre; Yim].
//
// Radix-16^3 four-step, packed f32x2, binary-decomposition twiddles (r12 math).
// Round 14: pass-1 global loads split into a front batch of 8 LDGs (one dft4
// group) + 24 LDGs that data-depend on batch-0's first value via an
// IEEE-unfoldable FFMA(r0, 0, 0) -> address offset. This cuts MLP_p1 32 -> 8,
// attacking the cross-CTA L1tex-queue spread (spr 1.36 -> ~1.12 per the B300
// spread model). Everything else identical to r12.
//
//   n = n1*256 + n2, k = k2*16 + k1, n2 = p1*16 + p2, k2 = q2*16 + q1.
// Pass 1 (t=n2):   A[k1] = DFT16_{n1}(x[n1*256+t]) * W4096^{t*k1}
// Exch 1 (pad 257)
// Pass 2 (k1,p2):  C[q1] = DFT16_{p1}(...) * W256^{p2*q1}
// Exch 2 ([q1*256+t])
// Pass 3 (k1,q1):  Y[q2*256 + t] = DFT16_{p2}(...)

#define NFFT 4096
#define TPB  256

typedef unsigned long long c64;   // packed complex: lo 32 = re, hi 32 = im

__device__ __forceinline__ c64 cpack(float re, float im) {
    c64 r;
    asm("mov.b64 %0, {%1, %2};" : "=l"(r) : "f"(re), "f"(im));
    return r;
}
__device__ __forceinline__ void cunpack(c64 v, float& re, float& im) {
    asm("mov.b64 {%0, %1}, %2;" : "=f"(re), "=f"(im) : "l"(v));
}
__device__ __forceinline__ c64 padd(c64 a, c64 b) {
    c64 r;
    asm("add.rn.f32x2 %0, %1, %2;" : "=l"(r) : "l"(a), "l"(b));
    return r;
}
__device__ __forceinline__ c64 pmul(c64 a, c64 b) {
    c64 r;
    asm("mul.rn.f32x2 %0, %1, %2;" : "=l"(r) : "l"(a), "l"(b));
    return r;
}
__device__ __forceinline__ c64 pfma(c64 a, c64 b, c64 c) {
    c64 r;
    asm("fma.rn.f32x2 %0, %1, %2, %3;" : "=l"(r) : "l"(a), "l"(b), "l"(c));
    return r;
}
__device__ __forceinline__ c64 pswap(c64 a) {   // (re,im) -> (im,re)
    c64 r;
    asm("{\n\t.reg .b32 lo, hi;\n\tmov.b64 {lo, hi}, %1;\n\tmov.b64 %0, {hi, lo};\n\t}"
        : "=l"(r) : "l"(a));
    return r;
}

#define K_NEG1 cpack(-1.0f, -1.0f)
#define K_PM   cpack( 1.0f, -1.0f)
#define K_MP   cpack(-1.0f,  1.0f)

__device__ __forceinline__ c64 psub(c64 a, c64 b) { return pfma(b, K_NEG1, a); }
// complex mul by twiddle held split: xx=(c,c), nyy=(-s,s)
__device__ __forceinline__ c64 cmul_t(c64 a, c64 xx, c64 nyy) {
    return pfma(a, xx, pmul(pswap(a), nyy));
}
// multiply by -i
__device__ __forceinline__ c64 cnegi(c64 a) { return pmul(pswap(a), K_PM); }

// forward DFT4 (W4 = -i), packed
__device__ __forceinline__ void dft4(c64 a, c64 b, c64 c, c64 d,
                                     c64& o0, c64& o1, c64& o2, c64& o3) {
    c64 s0 = padd(a, c);
    c64 s1 = psub(a, c);
    c64 s2 = padd(b, d);
    c64 s3 = psub(b, d);
    o0 = padd(s0, s2);
    o2 = psub(s0, s2);
    c64 s3r = pswap(s3);
    o1 = pfma(s3r, K_PM, s1);   // s1 - i*s3
    o3 = pfma(s3r, K_MP, s1);   // s1 + i*s3
}

// internal-twiddle + layer-2 of the 16-point DFT (layer-1 dft4s done inline)
__device__ __forceinline__ void fft16_tail(c64 a[4][4], c64 v[16]) {
    const float C1 = 0.92387953251128675613f;  // cos(pi/8)
    const float S1 = 0.38268343236508977173f;  // sin(pi/8)
    const float R  = 0.70710678118654752440f;  // sqrt(2)/2

    a[1][1] = cmul_t(a[1][1], cpack( C1,  C1), cpack( S1, -S1));
    a[1][2] = cmul_t(a[1][2], cpack(  R,   R), cpack(  R,  -R));
    a[1][3] = cmul_t(a[1][3], cpack( S1,  S1), cpack( C1, -C1));
    a[2][1] = cmul_t(a[2][1], cpack(  R,   R), cpack(  R,  -R));
    a[2][2] = cnegi(a[2][2]);
    a[2][3] = cmul_t(a[2][3], cpack( -R,  -R), cpack(  R,  -R));
    a[3][1] = cmul_t(a[3][1], cpack( S1,  S1), cpack( C1, -C1));
    a[3][2] = cmul_t(a[3][2], cpack( -R,  -R), cpack(  R,  -R));
    a[3][3] = cmul_t(a[3][3], cpack(-C1, -C1), cpack(-S1,  S1));

#pragma unroll
    for (int p = 0; p < 4; p++)
        dft4(a[0][p], a[1][p], a[2][p], a[3][p],
             v[p], v[4 + p], v[8 + p], v[12 + p]);
}

// full 16-point forward DFT, natural in -> natural out (passes 2 and 3)
__device__ __forceinline__ void fft16(c64 v[16]) {
    c64 a[4][4];
#pragma unroll
    for (int l = 0; l < 4; l++)
        dft4(v[l], v[l + 4], v[l + 8], v[l + 12],
             a[l][0], a[l][1], a[l][2], a[l][3]);
    fft16_tail(a, v);
}

// v[k] *= w^k, k=1..15, via binary decomposition (no serial chain).
__device__ __forceinline__ void twiddle16_bits(c64 v[16], float ang) {
    float s, c;
    __sincosf(ang, &s, &c);                       // MUFU; |ang| < 0.4
    float c2 = fmaf(c,  c,  -s  * s ),  s2 = 2.0f * c  * s;
    float c4 = fmaf(c2, c2, -s2 * s2),  s4 = 2.0f * c2 * s2;
    float c8 = fmaf(c4, c4, -s4 * s4),  s8 = 2.0f * c4 * s4;

    {
        const c64 xx = cpack(c, c), nn = cpack(-s, s);
#pragma unroll
        for (int k = 1; k < 16; k += 2)
            v[k] = cmul_t(v[k], xx, nn);
    }
    {
        const c64 xx = cpack(c2, c2), nn = cpack(-s2, s2);
#pragma unroll
        for (int k = 2; k < 16; k += 4) {
            v[k]     = cmul_t(v[k],     xx, nn);
            v[k + 1] = cmul_t(v[k + 1], xx, nn);
        }
    }
    {
        const c64 xx = cpack(c4, c4), nn = cpack(-s4, s4);
#pragma unroll
        for (int k = 4; k < 8; k++) {
            v[k]     = cmul_t(v[k],     xx, nn);
            v[k + 8] = cmul_t(v[k + 8], xx, nn);
        }
    }
    {
        const c64 xx = cpack(c8, c8), nn = cpack(-s8, s8);
#pragma unroll
        for (int k = 8; k < 16; k++)
            v[k] = cmul_t(v[k], xx, nn);
    }
}

__global__ void __launch_bounds__(TPB, 4)
fft4096_kernel(const float* __restrict__ xre,
               const float* __restrict__ xim,
               float* __restrict__ out,
               int batch) {
    __shared__ c64 sh[16 * 257];  // 32896 B (257-stride pad for exch 1)

    const int b = blockIdx.x;
    const int t = threadIdx.x;

    const float* xr = xre + (size_t)b * NFFT;
    const float* xi = xim + (size_t)b * NFFT;

    c64 v[16];
    c64 a[4][4];

    // ---- pass-1 loads + layer-1, chained: batch 0 (8 LDG) then batches 1..3
    //      whose addresses truly depend on batch-0's first value (unfoldable
    //      FFMA r0*0+0 -> int offset 0). MLP_p1: 32 -> 8.
    int doff;
    {
        const float* pr = xr + t;
        const float* pi = xi + t;
        float r0 = __ldcs(pr);
        float r1 = __ldcs(pr + 1024);
        float r2 = __ldcs(pr + 2048);
        float r3 = __ldcs(pr + 3072);
        float q0 = __ldcs(pi);
        float q1 = __ldcs(pi + 1024);
        float q2 = __ldcs(pi + 2048);
        float q3 = __ldcs(pi + 3072);
        float zf;
        asm("fma.rn.f32 %0, %1, 0f00000000, 0f00000000;" : "=f"(zf) : "f"(r0));
        doff = __float_as_int(zf);   // always 0, but ptxas cannot prove it
        dft4(cpack(r0, q0), cpack(r1, q1), cpack(r2, q2), cpack(r3, q3),
             a[0][0], a[0][1], a[0][2], a[0][3]);
    }
#pragma unroll
    for (int l = 1; l < 4; l++) {
        const float* pr = xr + l * 256 + t + doff;
        const float* pi = xi + l * 256 + t + doff;
        float r0 = __ldcs(pr);
        float r1 = __ldcs(pr + 1024);
        float r2 = __ldcs(pr + 2048);
        float r3 = __ldcs(pr + 3072);
        float q0 = __ldcs(pi);
        float q1 = __ldcs(pi + 1024);
        float q2 = __ldcs(pi + 2048);
        float q3 = __ldcs(pi + 3072);
        dft4(cpack(r0, q0), cpack(r1, q1), cpack(r2, q2), cpack(r3, q3),
             a[l][0], a[l][1], a[l][2], a[l][3]);
    }

    // ---- pass 1 tail + twiddle W4096^{t*k1} ----
    fft16_tail(a, v);
    twiddle16_bits(v, (float)t * (-6.2831853071795864769f / 4096.0f));

    // ---- exchange 1: sh[k1*257 + n2] ----
#pragma unroll
    for (int k1 = 0; k1 < 16; k1++)
        sh[k1 * 257 + t] = v[k1];
    __syncthreads();

    {
        const int k1 = t & 15;
        const int p2 = t >> 4;
#pragma unroll
        for (int p1 = 0; p1 < 16; p1++)
            v[p1] = sh[k1 * 257 + p1 * 16 + p2];

        // ---- pass 2: DFT16 over p1 -> q1, twiddle W256^{p2*q1} ----
        fft16(v);
        twiddle16_bits(v, (float)p2 * (-6.2831853071795864769f / 256.0f));
    }
    __syncthreads();

    // ---- exchange 2: sh[q1*256 + t] ----
#pragma unroll
    for (int q1 = 0; q1 < 16; q1++)
        sh[q1 * 256 + t] = v[q1];
    __syncthreads();

    {
        const int k1 = t & 15;
        const int q1 = t >> 4;
#pragma unroll
        for (int p2 = 0; p2 < 16; p2++)
            v[p2] = sh[q1 * 256 + p2 * 16 + k1];
    }

    // ---- pass 3: DFT16 over p2 -> q2;  Y[q2*256 + t] ----
    fft16(v);

    float* outre = out + (size_t)b * NFFT;
    float* outim = out + (size_t)batch * NFFT + (size_t)b * NFFT;
#pragma unroll
    for (int q2 = 0; q2 < 16; q2++) {
        float re, im;
        cunpack(v[q2], re, im);
        __stcs(&outre[q2 * 256 + t], re);
        __stcs(&outim[q2 * 256 + t], im);
    }
}

extern "C" void kernel_launch(void* const* d_in, const int* in_sizes, int n_in,
                              void* d_out, int out_size) {
    const float* xre = (const float*)d_in[0];
    const float* xim = (const float*)d_in[1];
    float* out = (float*)d_out;
    const int batch = in_sizes[0] / NFFT;

    fft4096_kernel<<<batch, TPB>>>(xre, xim, out, batch);
}

// round 15
// speedup vs baseline: 1.0501x; 1.0153x over previous
#include <cuda_runtime.h>
#include <math.h>

// Batched FFT: B=8192 rows, N=4096, complex fp32 (separate re/im), out = [Yre; Yim].
//
// Radix-16^3 four-step, packed f32x2 arithmetic, binary-decomposition twiddles
// (round-12 math, 82.46us kernel). Round 15: WAVE-1 CTA PHASE STAGGER.
// Co-resident CTAs (b mod sms equal, b/sms = 0..3 in wave 1) are launched
// phase-locked -> their DRAM-read bursts and compute windows align, idling
// DRAM ~26% of the time. Delay wave-1 CTA rank r by r*2600 cycles (thread 0
// spins on clock64, rest sleep at the barrier); later waves inherit the
// stagger through the work-stealing launch of successors.
//
//   n = n1*256 + n2, k = k2*16 + k1, n2 = p1*16 + p2, k2 = q2*16 + q1.
// Pass 1 (t=n2):   A[k1] = DFT16_{n1}(x[n1*256+t]) * W4096^{t*k1}
// Exch 1 (pad 257)
// Pass 2 (k1,p2):  C[q1] = DFT16_{p1}(...) * W256^{p2*q1}
// Exch 2 ([q1*256+t])
// Pass 3 (k1,q1):  Y[q2*256 + t] = DFT16_{p2}(...)

#define NFFT 4096
#define TPB  256

typedef unsigned long long c64;   // packed complex: lo 32 = re, hi 32 = im

__device__ __forceinline__ c64 cpack(float re, float im) {
    c64 r;
    asm("mov.b64 %0, {%1, %2};" : "=l"(r) : "f"(re), "f"(im));
    return r;
}
__device__ __forceinline__ void cunpack(c64 v, float& re, float& im) {
    asm("mov.b64 {%0, %1}, %2;" : "=f"(re), "=f"(im) : "l"(v));
}
__device__ __forceinline__ c64 padd(c64 a, c64 b) {
    c64 r;
    asm("add.rn.f32x2 %0, %1, %2;" : "=l"(r) : "l"(a), "l"(b));
    return r;
}
__device__ __forceinline__ c64 pmul(c64 a, c64 b) {
    c64 r;
    asm("mul.rn.f32x2 %0, %1, %2;" : "=l"(r) : "l"(a), "l"(b));
    return r;
}
__device__ __forceinline__ c64 pfma(c64 a, c64 b, c64 c) {
    c64 r;
    asm("fma.rn.f32x2 %0, %1, %2, %3;" : "=l"(r) : "l"(a), "l"(b), "l"(c));
    return r;
}
__device__ __forceinline__ c64 pswap(c64 a) {   // (re,im) -> (im,re)
    c64 r;
    asm("{\n\t.reg .b32 lo, hi;\n\tmov.b64 {lo, hi}, %1;\n\tmov.b64 %0, {hi, lo};\n\t}"
        : "=l"(r) : "l"(a));
    return r;
}

#define K_NEG1 cpack(-1.0f, -1.0f)
#define K_PM   cpack( 1.0f, -1.0f)
#define K_MP   cpack(-1.0f,  1.0f)

__device__ __forceinline__ c64 psub(c64 a, c64 b) { return pfma(b, K_NEG1, a); }
// complex mul by twiddle held split: xx=(c,c), nyy=(-s,s)
__device__ __forceinline__ c64 cmul_t(c64 a, c64 xx, c64 nyy) {
    return pfma(a, xx, pmul(pswap(a), nyy));
}
// multiply by -i
__device__ __forceinline__ c64 cnegi(c64 a) { return pmul(pswap(a), K_PM); }

// forward DFT4 (W4 = -i), packed
__device__ __forceinline__ void dft4(c64 a, c64 b, c64 c, c64 d,
                                     c64& o0, c64& o1, c64& o2, c64& o3) {
    c64 s0 = padd(a, c);
    c64 s1 = psub(a, c);
    c64 s2 = padd(b, d);
    c64 s3 = psub(b, d);
    o0 = padd(s0, s2);
    o2 = psub(s0, s2);
    c64 s3r = pswap(s3);
    o1 = pfma(s3r, K_PM, s1);   // s1 - i*s3
    o3 = pfma(s3r, K_MP, s1);   // s1 + i*s3
}

// 16-point forward DFT, natural in -> natural out (radix-4 x radix-4), packed.
__device__ __forceinline__ void fft16(c64 v[16]) {
    const float C1 = 0.92387953251128675613f;  // cos(pi/8)
    const float S1 = 0.38268343236508977173f;  // sin(pi/8)
    const float R  = 0.70710678118654752440f;  // sqrt(2)/2

    c64 a[4][4];
#pragma unroll
    for (int l = 0; l < 4; l++)
        dft4(v[l], v[l + 4], v[l + 8], v[l + 12],
             a[l][0], a[l][1], a[l][2], a[l][3]);

    a[1][1] = cmul_t(a[1][1], cpack( C1,  C1), cpack( S1, -S1));
    a[1][2] = cmul_t(a[1][2], cpack(  R,   R), cpack(  R,  -R));
    a[1][3] = cmul_t(a[1][3], cpack( S1,  S1), cpack( C1, -C1));
    a[2][1] = cmul_t(a[2][1], cpack(  R,   R), cpack(  R,  -R));
    a[2][2] = cnegi(a[2][2]);
    a[2][3] = cmul_t(a[2][3], cpack( -R,  -R), cpack(  R,  -R));
    a[3][1] = cmul_t(a[3][1], cpack( S1,  S1), cpack( C1, -C1));
    a[3][2] = cmul_t(a[3][2], cpack( -R,  -R), cpack(  R,  -R));
    a[3][3] = cmul_t(a[3][3], cpack(-C1, -C1), cpack(-S1,  S1));

#pragma unroll
    for (int p = 0; p < 4; p++)
        dft4(a[0][p], a[1][p], a[2][p], a[3][p],
             v[p], v[4 + p], v[8 + p], v[12 + p]);
}

// v[k] *= w^k, k=1..15, via binary decomposition (no serial chain).
__device__ __forceinline__ void twiddle16_bits(c64 v[16], float ang) {
    float s, c;
    __sincosf(ang, &s, &c);                       // MUFU; |ang| < 0.4
    float c2 = fmaf(c,  c,  -s  * s ),  s2 = 2.0f * c  * s;
    float c4 = fmaf(c2, c2, -s2 * s2),  s4 = 2.0f * c2 * s2;
    float c8 = fmaf(c4, c4, -s4 * s4),  s8 = 2.0f * c4 * s4;

    {
        const c64 xx = cpack(c, c), nn = cpack(-s, s);
#pragma unroll
        for (int k = 1; k < 16; k += 2)
            v[k] = cmul_t(v[k], xx, nn);
    }
    {
        const c64 xx = cpack(c2, c2), nn = cpack(-s2, s2);
#pragma unroll
        for (int k = 2; k < 16; k += 4) {
            v[k]     = cmul_t(v[k],     xx, nn);
            v[k + 1] = cmul_t(v[k + 1], xx, nn);
        }
    }
    {
        const c64 xx = cpack(c4, c4), nn = cpack(-s4, s4);
#pragma unroll
        for (int k = 4; k < 8; k++) {
            v[k]     = cmul_t(v[k],     xx, nn);
            v[k + 8] = cmul_t(v[k + 8], xx, nn);
        }
    }
    {
        const c64 xx = cpack(c8, c8), nn = cpack(-s8, s8);
#pragma unroll
        for (int k = 8; k < 16; k++)
            v[k] = cmul_t(v[k], xx, nn);
    }
}

__global__ void __launch_bounds__(TPB, 4)
fft4096_kernel(const float* __restrict__ xre,
               const float* __restrict__ xim,
               float* __restrict__ out,
               int batch, int sms) {
    __shared__ c64 sh[16 * 257];  // 32896 B (257-stride pad for exch 1)

    const int b = blockIdx.x;
    const int t = threadIdx.x;

    // ---- wave-1 phase stagger: co-resident quartet = same (b mod sms),
    //      rank r = b/sms in {0..3}. Delay rank r by r*2600 cycles. ----
    if (b < 4 * sms) {
        int rank = b / sms;
        if (rank > 0) {
            if (t == 0) {
                long long d = (long long)rank * 2600;
                long long t0 = clock64();
                while (clock64() - t0 < d) { }
            }
            __syncthreads();
        }
    }

    const float* xr = xre + (size_t)b * NFFT;
    const float* xi = xim + (size_t)b * NFFT;

    c64 v[16];
#pragma unroll
    for (int n1 = 0; n1 < 16; n1++)
        v[n1] = cpack(__ldcs(&xr[n1 * 256 + t]), __ldcs(&xi[n1 * 256 + t]));

    // ---- pass 1: DFT16 over n1 (thread t = n2), twiddle W4096^{t*k1} ----
    fft16(v);
    twiddle16_bits(v, (float)t * (-6.2831853071795864769f / 4096.0f));

    // ---- exchange 1: sh[k1*257 + n2] ----
#pragma unroll
    for (int k1 = 0; k1 < 16; k1++)
        sh[k1 * 257 + t] = v[k1];
    __syncthreads();

    {
        const int k1 = t & 15;
        const int p2 = t >> 4;
#pragma unroll
        for (int p1 = 0; p1 < 16; p1++)
            v[p1] = sh[k1 * 257 + p1 * 16 + p2];

        // ---- pass 2: DFT16 over p1 -> q1, twiddle W256^{p2*q1} ----
        fft16(v);
        twiddle16_bits(v, (float)p2 * (-6.2831853071795864769f / 256.0f));
    }
    __syncthreads();

    // ---- exchange 2: sh[q1*256 + t] ----
#pragma unroll
    for (int q1 = 0; q1 < 16; q1++)
        sh[q1 * 256 + t] = v[q1];
    __syncthreads();

    {
        const int k1 = t & 15;
        const int q1 = t >> 4;
#pragma unroll
        for (int p2 = 0; p2 < 16; p2++)
            v[p2] = sh[q1 * 256 + p2 * 16 + k1];
    }

    // ---- pass 3: DFT16 over p2 -> q2;  Y[q2*256 + t] ----
    fft16(v);

    float* outre = out + (size_t)b * NFFT;
    float* outim = out + (size_t)batch * NFFT + (size_t)b * NFFT;
#pragma unroll
    for (int q2 = 0; q2 < 16; q2++) {
        float re, im;
        cunpack(v[q2], re, im);
        __stcs(&outre[q2 * 256 + t], re);
        __stcs(&outim[q2 * 256 + t], im);
    }
}

extern "C" void kernel_launch(void* const* d_in, const int* in_sizes, int n_in,
                              void* d_out, int out_size) {
    const float* xre = (const float*)d_in[0];
    const float* xim = (const float*)d_in[1];
    float* out = (float*)d_out;
    const int batch = in_sizes[0] / NFFT;

    int sms = 0;
    cudaDeviceGetAttribute(&sms, cudaDevAttrMultiProcessorCount, 0);
    if (sms <= 0) sms = 148;

    fft4096_kernel<<<batch, TPB>>>(xre, xim, out, batch, sms);
}